// round 6
// baseline (speedup 1.0000x reference)
#include <cuda_runtime.h>
#include <math.h>
#include <stdint.h>

// Problem constants
#define NB     8
#define TT     64
#define JJ     25
#define CC     256       // D_MODEL
#define DI     512       // D_INNER
#define DS     16        // D_STATE
#define DTR    16        // DT_RANK
#define BTOT   (NB*JJ)   // 200
#define NROWS  (BTOT*TT) // 12800

// ---------------- scratch ----------------
__device__ float g_xc2[NROWS * DI];
__device__ float g_z  [NROWS * DI];
__device__ float g_dt [NROWS * DI];
__device__ float g_y  [NROWS * DI];
__device__ float g_Bm [NROWS * DS];
__device__ float g_Cm [NROWS * DS];

// ---------------- helpers ----------------
__device__ __forceinline__ float silu_f(float v) { return v / (1.0f + __expf(-v)); }
__device__ __forceinline__ float softplus_f(float v) {
    return fmaxf(v, 0.0f) + log1pf(__expf(-fabsf(v)));
}
__device__ __forceinline__ uint32_t f2t(float f) {
    uint32_t u; asm("cvt.rna.tf32.f32 %0, %1;" : "=r"(u) : "f"(f)); return u;
}
__device__ __forceinline__ void mma8(float* c, uint32_t a0, uint32_t a1, uint32_t a2,
                                     uint32_t a3, uint32_t b0, uint32_t b1) {
    asm volatile(
        "mma.sync.aligned.m16n8k8.row.col.f32.tf32.tf32.f32 "
        "{%0,%1,%2,%3},{%4,%5,%6,%7},{%8,%9},{%0,%1,%2,%3};"
        : "+f"(c[0]), "+f"(c[1]), "+f"(c[2]), "+f"(c[3])
        : "r"(a0), "r"(a1), "r"(a2), "r"(a3), "r"(b0), "r"(b1));
}

// ---------------- k1: in-proj GEMM (tf32 mma, paired frags) + fused conv/SiLU ------
// Block: one sequence b (64 rows) x 128 e-cols. xs overlays sA2/sB2 (union) so
// smem stays at 33 KB. Paired uint2 layout: element l of pair = (k, k+4).
__global__ __launch_bounds__(256) void k1_gemm_in(const float* __restrict__ x,
                                                  const float* __restrict__ W,
                                                  const float* __restrict__ conv_w,
                                                  const float* __restrict__ conv_b) {
    __shared__ __align__(16) char smem[33536];
    uint2* sA2 = (uint2*)smem;               // [64][17]
    uint2* sB2 = (uint2*)(smem + 8704);      // [128][17]
    float* xs  = (float*)smem;               // [64][129] (overlay, used post-GEMM)

    const int tid = threadIdx.x, lane = tid & 31, warp = tid >> 5;
    const int lr = lane >> 2, lk = lane & 3;
    const int b = blockIdx.x, n0 = blockIdx.y * 128;
    const int n = b / 25, j = b - n * 25;
    const float* xbase = x + ((size_t)(n * TT) * JJ + j) * CC;
    const int wr = (warp >> 2) * 32, wc = (warp & 3) * 32;

    float acc[2][4][4];
    #pragma unroll
    for (int i = 0; i < 2; i++)
        #pragma unroll
        for (int jj = 0; jj < 4; jj++)
            #pragma unroll
            for (int q = 0; q < 4; q++) acc[i][jj][q] = 0.0f;

    const int ar = tid >> 2, kk_a = tid & 3;   // A: row ar, k-block kk_a (8 floats)
    const int br = tid >> 1, half = tid & 1;   // B: row br, k-half (16 floats)

    float abuf[8], bbuf[16];
    auto gload = [&](int c0) {
        const float4* p = (const float4*)(xbase + (size_t)ar * JJ * CC + c0 + kk_a * 8);
        float4 v0 = p[0], v1 = p[1];
        abuf[0]=v0.x; abuf[1]=v0.y; abuf[2]=v0.z; abuf[3]=v0.w;
        abuf[4]=v1.x; abuf[5]=v1.y; abuf[6]=v1.z; abuf[7]=v1.w;
        const float4* q = (const float4*)(W + (size_t)(n0 + br) * CC + c0 + half * 16);
        #pragma unroll
        for (int t = 0; t < 4; t++) {
            float4 v = q[t];
            bbuf[4*t]=v.x; bbuf[4*t+1]=v.y; bbuf[4*t+2]=v.z; bbuf[4*t+3]=v.w;
        }
    };

    gload(0);
    for (int c0 = 0; c0 < CC; c0 += 32) {
        #pragma unroll
        for (int l = 0; l < 4; l++)
            sA2[ar * 17 + kk_a * 4 + l] = make_uint2(f2t(abuf[l]), f2t(abuf[l + 4]));
        #pragma unroll
        for (int kl = 0; kl < 2; kl++)
            #pragma unroll
            for (int l = 0; l < 4; l++)
                sB2[br * 17 + (half * 2 + kl) * 4 + l] =
                    make_uint2(f2t(bbuf[kl * 8 + l]), f2t(bbuf[kl * 8 + l + 4]));
        __syncthreads();
        if (c0 + 32 < CC) gload(c0 + 32);
        #pragma unroll
        for (int kk = 0; kk < 4; kk++) {
            uint2 av0[2], av1[2];
            #pragma unroll
            for (int i = 0; i < 2; i++) {
                av0[i] = sA2[(wr + 16*i + lr    ) * 17 + kk * 4 + lk];
                av1[i] = sA2[(wr + 16*i + 8 + lr) * 17 + kk * 4 + lk];
            }
            #pragma unroll
            for (int jj = 0; jj < 4; jj++) {
                uint2 bv = sB2[(wc + 8*jj + lr) * 17 + kk * 4 + lk];
                #pragma unroll
                for (int i = 0; i < 2; i++)
                    mma8(acc[i][jj], av0[i].x, av1[i].x, av0[i].y, av1[i].y, bv.x, bv.y);
            }
        }
        __syncthreads();
    }

    if (n0 < DI) {
        // xc branch: stage into xs (overlays sA2/sB2), conv + bias + SiLU locally
        #pragma unroll
        for (int i = 0; i < 2; i++) {
            const int r0 = wr + 16*i + lr, r1 = r0 + 8;
            #pragma unroll
            for (int jj = 0; jj < 4; jj++) {
                const int col = wc + 8*jj + 2*lk;
                xs[r0 * 129 + col]     = acc[i][jj][0];
                xs[r0 * 129 + col + 1] = acc[i][jj][1];
                xs[r1 * 129 + col]     = acc[i][jj][2];
                xs[r1 * 129 + col + 1] = acc[i][jj][3];
            }
        }
        __syncthreads();
        for (int idx = tid; idx < 64 * 128; idx += 256) {
            const int t = idx >> 7, c = idx & 127;
            const int d = n0 + c;
            float s = conv_b[d];
            #pragma unroll
            for (int k = 0; k < 4; k++) {
                int tt = t - 3 + k;
                if (tt >= 0) s = fmaf(conv_w[d * 4 + k], xs[tt * 129 + c], s);
            }
            g_xc2[(size_t)(b * TT + t) * DI + d] = silu_f(s);
        }
    } else {
        const int eoff = n0 - DI;
        #pragma unroll
        for (int i = 0; i < 2; i++) {
            const int r0 = wr + 16*i + lr, r1 = r0 + 8;
            const size_t m0r = (size_t)(b * TT + r0) * DI;
            const size_t m1r = (size_t)(b * TT + r1) * DI;
            #pragma unroll
            for (int jj = 0; jj < 4; jj++) {
                const int col = eoff + wc + 8*jj + 2*lk;
                *(float2*)&g_z[m0r + col] = make_float2(acc[i][jj][0], acc[i][jj][1]);
                *(float2*)&g_z[m1r + col] = make_float2(acc[i][jj][2], acc[i][jj][3]);
            }
        }
    }
}

// ---------------- k3: x_dbl projection + dt projection (float4 smem) --------------
__global__ __launch_bounds__(256) void k3_xproj(const float* __restrict__ Wx,
                                                const float* __restrict__ Wdt,
                                                const float* __restrict__ bdt) {
    __shared__ __align__(16) float buf[13568];
    float* sX = buf;                      // [64][68]
    float* sW = buf + 64 * 68;            // [48][68]
    const int tid = threadIdx.x;
    const int m0 = blockIdx.x * 64;
    const int row = tid >> 2, c0 = (tid & 3) * 12;

    float acc[12];
    #pragma unroll
    for (int i = 0; i < 12; i++) acc[i] = 0.0f;

    for (int k0 = 0; k0 < DI; k0 += 64) {
        __syncthreads();
        for (int idx = tid; idx < 64 * 16; idx += 256) {
            int r = idx >> 4, q = idx & 15;
            *(float4*)&sX[r * 68 + q * 4] =
                *(const float4*)&g_xc2[(size_t)(m0 + r) * DI + k0 + q * 4];
        }
        for (int idx = tid; idx < 48 * 16; idx += 256) {
            int r = idx >> 4, q = idx & 15;
            *(float4*)&sW[r * 68 + q * 4] =
                *(const float4*)&Wx[(size_t)r * DI + k0 + q * 4];
        }
        __syncthreads();
        #pragma unroll 4
        for (int q = 0; q < 16; q++) {
            float4 xv = *(const float4*)&sX[row * 68 + q * 4];
            #pragma unroll
            for (int i = 0; i < 12; i++) {
                float4 wv = *(const float4*)&sW[(c0 + i) * 68 + q * 4];
                acc[i] = fmaf(xv.x, wv.x, acc[i]);
                acc[i] = fmaf(xv.y, wv.y, acc[i]);
                acc[i] = fmaf(xv.z, wv.z, acc[i]);
                acc[i] = fmaf(xv.w, wv.w, acc[i]);
            }
        }
    }
    __syncthreads();

    float* sD   = buf;                    // [64][52]
    float* sWdt = buf + 64 * 52;          // [512][20]
    #pragma unroll
    for (int i = 0; i < 12; i++) sD[row * 52 + c0 + i] = acc[i];
    for (int idx = tid; idx < 512 * 4; idx += 256) {
        int d = idx >> 2, q = idx & 3;
        *(float4*)&sWdt[d * 20 + q * 4] = *(const float4*)&Wdt[d * 16 + q * 4];
    }
    __syncthreads();

    for (int idx = tid; idx < 64 * 32; idx += 256) {
        int r = idx >> 5, v = idx & 31;
        float val = sD[r * 52 + DTR + v];
        if (v < 16) g_Bm[(size_t)(m0 + r) * DS + v]        = val;
        else        g_Cm[(size_t)(m0 + r) * DS + (v - 16)] = val;
    }
    for (int idx = tid; idx < 64 * DI; idx += 256) {
        int r = idx >> 9, d = idx & 511;
        float a = bdt[d];
        #pragma unroll
        for (int q = 0; q < 4; q++) {
            float4 dv = *(const float4*)&sD[r * 52 + q * 4];
            float4 wv = *(const float4*)&sWdt[d * 20 + q * 4];
            a = fmaf(dv.x, wv.x, a);
            a = fmaf(dv.y, wv.y, a);
            a = fmaf(dv.z, wv.z, a);
            a = fmaf(dv.w, wv.w, a);
        }
        g_dt[(size_t)(m0 + r) * DI + d] = softplus_f(a);
    }
}

// ---------------- k4: selective scan ----------------
// grid (200, 4), block 128: one channel per thread. Fast path exploits
// A = -(1..16): dA_s = w^(s+1), w = exp(-dt)  (one MUFU per (d,t)).
__global__ __launch_bounds__(128) void k4_scan(const float* __restrict__ A_log,
                                               const float* __restrict__ D_skip) {
    const int tid = threadIdx.x;
    const int b   = blockIdx.x;
    const int d   = blockIdx.y * 128 + tid;

    float Aa[DS], h[DS];
    bool fast = true;
    #pragma unroll
    for (int s = 0; s < DS; s++) {
        Aa[s] = -__expf(A_log[d * DS + s]);
        fast = fast && (fabsf(Aa[s] + (float)(s + 1)) < 1e-4f * (float)(s + 1));
        h[s] = 0.0f;
    }
    const float Dk = D_skip[d];

    const size_t rowbase = (size_t)b * TT * DI + d;
    const float* pdt = g_dt  + rowbase;
    const float* pxc = g_xc2 + rowbase;
    const float* pz  = g_z   + rowbase;
    float*       py  = g_y   + rowbase;
    const float4* pB = (const float4*)(g_Bm + (size_t)b * TT * DS);
    const float4* pC = (const float4*)(g_Cm + (size_t)b * TT * DS);

    if (fast) {
        for (int t = 0; t < TT; t++) {
            const size_t o = (size_t)t * DI;
            float dt = pdt[o], xc = pxc[o], z = pz[o];
            float Bv[DS], Cv[DS];
            #pragma unroll
            for (int q = 0; q < 4; q++) {
                float4 bq = pB[t*4 + q], cq = pC[t*4 + q];
                Bv[4*q]=bq.x; Bv[4*q+1]=bq.y; Bv[4*q+2]=bq.z; Bv[4*q+3]=bq.w;
                Cv[4*q]=cq.x; Cv[4*q+1]=cq.y; Cv[4*q+2]=cq.z; Cv[4*q+3]=cq.w;
            }
            const float du = dt * xc;
            const float w = __expf(-dt);
            float pw = w, y = 0.0f;
            #pragma unroll
            for (int s = 0; s < DS; s++) {
                h[s] = fmaf(pw, h[s], du * Bv[s]);
                y    = fmaf(h[s], Cv[s], y);
                pw  *= w;
            }
            y = fmaf(xc, Dk, y);
            py[o] = y * silu_f(z);
        }
    } else {
        for (int t = 0; t < TT; t++) {
            const size_t o = (size_t)t * DI;
            float dt = pdt[o], xc = pxc[o], z = pz[o];
            float Bv[DS], Cv[DS];
            #pragma unroll
            for (int q = 0; q < 4; q++) {
                float4 bq = pB[t*4 + q], cq = pC[t*4 + q];
                Bv[4*q]=bq.x; Bv[4*q+1]=bq.y; Bv[4*q+2]=bq.z; Bv[4*q+3]=bq.w;
                Cv[4*q]=cq.x; Cv[4*q+1]=cq.y; Cv[4*q+2]=cq.z; Cv[4*q+3]=cq.w;
            }
            const float du = dt * xc;
            float y = 0.0f;
            #pragma unroll
            for (int s = 0; s < DS; s++) {
                float dA = __expf(dt * Aa[s]);
                h[s] = fmaf(dA, h[s], du * Bv[s]);
                y    = fmaf(h[s], Cv[s], y);
            }
            y = fmaf(xc, Dk, y);
            py[o] = y * silu_f(z);
        }
    }
}

// ---------------- k5: out-proj GEMM (tf32 mma, paired frags, 64 rows) -------------
// Block = one sequence (64 rows) x full 256 cols; RMSNorm block-local. grid 200.
__global__ __launch_bounds__(256) void k5_gemm_out(const float* __restrict__ x,
                                                   const float* __restrict__ W,
                                                   const float* __restrict__ ln_w,
                                                   float* __restrict__ out) {
    __shared__ uint2 sA2[64 * 17];    // 8704 B
    __shared__ uint2 sB2[256 * 17];   // 34816 B
    __shared__ float rowsq[64];
    const int tid = threadIdx.x, lane = tid & 31, warp = tid >> 5;
    const int lr = lane >> 2, lk = lane & 3;
    const int m0 = blockIdx.x * 64;
    const int wr = (warp >> 2) * 32, wc = (warp & 3) * 64;

    if (tid < 64) rowsq[tid] = 0.0f;

    float acc[2][8][4];
    #pragma unroll
    for (int i = 0; i < 2; i++)
        #pragma unroll
        for (int jj = 0; jj < 8; jj++)
            #pragma unroll
            for (int q = 0; q < 4; q++) acc[i][jj][q] = 0.0f;

    const int ar = tid >> 2, kk_a = tid & 3;
    const int br = tid;

    for (int d0 = 0; d0 < DI; d0 += 32) {
        __syncthreads();
        {
            const float4* p = (const float4*)&g_y[(size_t)(m0 + ar) * DI + d0 + kk_a * 8];
            float4 v0 = p[0], v1 = p[1];
            sA2[ar * 17 + kk_a * 4 + 0] = make_uint2(f2t(v0.x), f2t(v1.x));
            sA2[ar * 17 + kk_a * 4 + 1] = make_uint2(f2t(v0.y), f2t(v1.y));
            sA2[ar * 17 + kk_a * 4 + 2] = make_uint2(f2t(v0.z), f2t(v1.z));
            sA2[ar * 17 + kk_a * 4 + 3] = make_uint2(f2t(v0.w), f2t(v1.w));
        }
        {
            const float4* p = (const float4*)(W + (size_t)br * DI + d0);
            #pragma unroll
            for (int kk = 0; kk < 4; kk++) {
                float4 v0 = p[2*kk], v1 = p[2*kk + 1];
                sB2[br * 17 + kk * 4 + 0] = make_uint2(f2t(v0.x), f2t(v1.x));
                sB2[br * 17 + kk * 4 + 1] = make_uint2(f2t(v0.y), f2t(v1.y));
                sB2[br * 17 + kk * 4 + 2] = make_uint2(f2t(v0.z), f2t(v1.z));
                sB2[br * 17 + kk * 4 + 3] = make_uint2(f2t(v0.w), f2t(v1.w));
            }
        }
        __syncthreads();
        #pragma unroll
        for (int kk = 0; kk < 4; kk++) {
            uint2 av0[2], av1[2];
            #pragma unroll
            for (int i = 0; i < 2; i++) {
                av0[i] = sA2[(wr + 16*i + lr    ) * 17 + kk * 4 + lk];
                av1[i] = sA2[(wr + 16*i + 8 + lr) * 17 + kk * 4 + lk];
            }
            #pragma unroll
            for (int jj = 0; jj < 8; jj++) {
                uint2 bv = sB2[(wc + 8*jj + lr) * 17 + kk * 4 + lk];
                #pragma unroll
                for (int i = 0; i < 2; i++)
                    mma8(acc[i][jj], av0[i].x, av1[i].x, av0[i].y, av1[i].y, bv.x, bv.y);
            }
        }
    }

    // per-row sum of squares
    #pragma unroll
    for (int i = 0; i < 2; i++) {
        float s0 = 0.0f, s1 = 0.0f;
        #pragma unroll
        for (int jj = 0; jj < 8; jj++) {
            s0 += acc[i][jj][0]*acc[i][jj][0] + acc[i][jj][1]*acc[i][jj][1];
            s1 += acc[i][jj][2]*acc[i][jj][2] + acc[i][jj][3]*acc[i][jj][3];
        }
        s0 += __shfl_xor_sync(0xffffffffu, s0, 1); s0 += __shfl_xor_sync(0xffffffffu, s0, 2);
        s1 += __shfl_xor_sync(0xffffffffu, s1, 1); s1 += __shfl_xor_sync(0xffffffffu, s1, 2);
        if (lk == 0) {
            atomicAdd(&rowsq[wr + 16*i + lr], s0);
            atomicAdd(&rowsq[wr + 16*i + 8 + lr], s1);
        }
    }
    __syncthreads();

    const int b = blockIdx.x;
    const int n = b / 25, j = b - n * 25;
    #pragma unroll
    for (int i = 0; i < 2; i++) {
        const int r0 = wr + 16*i + lr, r1 = r0 + 8;
        float rms0 = rsqrtf(rowsq[r0] * (1.0f / CC) + 1e-6f);
        float rms1 = rsqrtf(rowsq[r1] * (1.0f / CC) + 1e-6f);
        const size_t g0 = ((size_t)(n * TT + r0) * JJ + j) * CC;
        const size_t g1 = ((size_t)(n * TT + r1) * JJ + j) * CC;
        #pragma unroll
        for (int jj = 0; jj < 8; jj++) {
            const int col = wc + 8*jj + 2*lk;
            float2 lw = *(const float2*)&ln_w[col];
            float2 x0 = *(const float2*)&x[g0 + col];
            float2 x1 = *(const float2*)&x[g1 + col];
            *(float2*)&out[g0 + col] = make_float2(fmaf(acc[i][jj][0]*rms0, lw.x, x0.x),
                                                   fmaf(acc[i][jj][1]*rms0, lw.y, x0.y));
            *(float2*)&out[g1 + col] = make_float2(fmaf(acc[i][jj][2]*rms1, lw.x, x1.x),
                                                   fmaf(acc[i][jj][3]*rms1, lw.y, x1.y));
        }
    }
}

// ---------------- launch ----------------
extern "C" void kernel_launch(void* const* d_in, const int* in_sizes, int n_in,
                              void* d_out, int out_size) {
    const float* x      = (const float*)d_in[0];
    const float* W_in   = (const float*)d_in[1];
    const float* conv_w = (const float*)d_in[2];
    const float* conv_b = (const float*)d_in[3];
    const float* W_xprj = (const float*)d_in[4];
    const float* W_dt   = (const float*)d_in[5];
    const float* b_dt   = (const float*)d_in[6];
    const float* A_log  = (const float*)d_in[7];
    const float* D_skip = (const float*)d_in[8];
    const float* W_out  = (const float*)d_in[9];
    const float* ln_w   = (const float*)d_in[10];
    float* out = (float*)d_out;

    k1_gemm_in<<<dim3(BTOT, 8), 256>>>(x, W_in, conv_w, conv_b);
    k3_xproj<<<BTOT, 256>>>(W_xprj, W_dt, b_dt);
    k4_scan<<<dim3(BTOT, 4), 128>>>(A_log, D_skip);
    k5_gemm_out<<<BTOT, 256>>>(x, W_out, ln_w, out);
}

// round 10
// speedup vs baseline: 1.1875x; 1.1875x over previous
#include <cuda_runtime.h>
#include <math.h>
#include <stdint.h>

// Problem constants
#define NB     8
#define TT     64
#define JJ     25
#define CC     256       // D_MODEL
#define DI     512       // D_INNER
#define DS     16        // D_STATE
#define DTR    16        // DT_RANK
#define BTOT   (NB*JJ)   // 200
#define NROWS  (BTOT*TT) // 12800

// ---------------- scratch ----------------
__device__ float g_xc [NROWS * DI];
__device__ float g_xc2[NROWS * DI];
__device__ float g_z  [NROWS * DI];
__device__ float g_dt [NROWS * DI];
__device__ float g_y  [NROWS * DI];
__device__ float g_Bm [NROWS * DS];
__device__ float g_Cm [NROWS * DS];

// ---------------- helpers ----------------
__device__ __forceinline__ float silu_f(float v) { return v / (1.0f + __expf(-v)); }
__device__ __forceinline__ float softplus_f(float v) {
    return fmaxf(v, 0.0f) + log1pf(__expf(-fabsf(v)));
}
__device__ __forceinline__ uint32_t f2t(float f) {
    uint32_t u; asm("cvt.rna.tf32.f32 %0, %1;" : "=r"(u) : "f"(f)); return u;
}
__device__ __forceinline__ void mma8(float* c, uint32_t a0, uint32_t a1, uint32_t a2,
                                     uint32_t a3, uint32_t b0, uint32_t b1) {
    asm volatile(
        "mma.sync.aligned.m16n8k8.row.col.f32.tf32.tf32.f32 "
        "{%0,%1,%2,%3},{%4,%5,%6,%7},{%8,%9},{%0,%1,%2,%3};"
        : "+f"(c[0]), "+f"(c[1]), "+f"(c[2]), "+f"(c[3])
        : "r"(a0), "r"(a1), "r"(a2), "r"(a3), "r"(b0), "r"(b1));
}

// ---------------- k1: in-projection GEMM (tf32 mma) — 383us-build verbatim ----------
__global__ __launch_bounds__(256) void k1_gemm_in(const float* __restrict__ x,
                                                  const float* __restrict__ W) {
    __shared__ uint32_t sA[64][36];
    __shared__ uint32_t sB[128][36];
    const int tid = threadIdx.x, lane = tid & 31, warp = tid >> 5;
    const int lr = lane >> 2, lk = lane & 3;
    const int b = blockIdx.x, n0 = blockIdx.y * 128;
    const int n = b / 25, j = b - n * 25;
    const float* xbase = x + ((size_t)(n * TT) * JJ + j) * CC;
    const int wr = (warp >> 2) * 32, wc = (warp & 3) * 32;

    float acc[2][4][4];
    #pragma unroll
    for (int i = 0; i < 2; i++)
        #pragma unroll
        for (int jj = 0; jj < 4; jj++)
            #pragma unroll
            for (int q = 0; q < 4; q++) acc[i][jj][q] = 0.0f;

    const int ar = tid >> 2, ac = (tid & 3) * 8;
    const int br = tid >> 1, bc = (tid & 1) * 16;

    for (int c0 = 0; c0 < CC; c0 += 32) {
        __syncthreads();
        {
            const float4* p = (const float4*)(xbase + (size_t)ar * JJ * CC + c0 + ac);
            float4 v0 = p[0], v1 = p[1];
            sA[ar][ac+0]=f2t(v0.x); sA[ar][ac+1]=f2t(v0.y); sA[ar][ac+2]=f2t(v0.z); sA[ar][ac+3]=f2t(v0.w);
            sA[ar][ac+4]=f2t(v1.x); sA[ar][ac+5]=f2t(v1.y); sA[ar][ac+6]=f2t(v1.z); sA[ar][ac+7]=f2t(v1.w);
        }
        {
            const float4* p = (const float4*)(W + (size_t)(n0 + br) * CC + c0 + bc);
            #pragma unroll
            for (int q = 0; q < 4; q++) {
                float4 v = p[q];
                sB[br][bc+4*q+0]=f2t(v.x); sB[br][bc+4*q+1]=f2t(v.y);
                sB[br][bc+4*q+2]=f2t(v.z); sB[br][bc+4*q+3]=f2t(v.w);
            }
        }
        __syncthreads();
        #pragma unroll
        for (int kk = 0; kk < 4; kk++) {
            const int k0 = kk * 8;
            uint32_t a[2][4], bb[4][2];
            #pragma unroll
            for (int i = 0; i < 2; i++) {
                a[i][0] = sA[wr+16*i+lr  ][k0+lk];
                a[i][1] = sA[wr+16*i+8+lr][k0+lk];
                a[i][2] = sA[wr+16*i+lr  ][k0+lk+4];
                a[i][3] = sA[wr+16*i+8+lr][k0+lk+4];
            }
            #pragma unroll
            for (int jj = 0; jj < 4; jj++) {
                bb[jj][0] = sB[wc+8*jj+lr][k0+lk];
                bb[jj][1] = sB[wc+8*jj+lr][k0+lk+4];
            }
            #pragma unroll
            for (int i = 0; i < 2; i++)
                #pragma unroll
                for (int jj = 0; jj < 4; jj++)
                    mma8(acc[i][jj], a[i][0], a[i][1], a[i][2], a[i][3], bb[jj][0], bb[jj][1]);
        }
    }

    float* dst; int eoff;
    if (n0 < DI) { dst = g_xc; eoff = n0; } else { dst = g_z; eoff = n0 - DI; }
    #pragma unroll
    for (int i = 0; i < 2; i++) {
        const int r0 = wr + 16*i + lr, r1 = r0 + 8;
        const size_t m0r = (size_t)(b * TT + r0) * DI;
        const size_t m1r = (size_t)(b * TT + r1) * DI;
        #pragma unroll
        for (int jj = 0; jj < 4; jj++) {
            const int col = eoff + wc + 8*jj + 2*lk;
            *(float2*)&dst[m0r + col] = make_float2(acc[i][jj][0], acc[i][jj][1]);
            *(float2*)&dst[m1r + col] = make_float2(acc[i][jj][2], acc[i][jj][3]);
        }
    }
}

// ---------------- k2: depthwise causal conv + bias + SiLU — 383us-build verbatim ----
__global__ void k2_conv(const float* __restrict__ conv_w,
                        const float* __restrict__ conv_b) {
    int idx = blockIdx.x * blockDim.x + threadIdx.x;
    if (idx >= NROWS * DI) return;
    int d = idx & (DI - 1);
    int m = idx >> 9;
    int t = m & 63;
    float s = conv_b[d];
    #pragma unroll
    for (int k = 0; k < 4; k++) {
        int tt = t - 3 + k;
        if (tt >= 0) s = fmaf(conv_w[d * 4 + k], g_xc[(size_t)(m - 3 + k) * DI + d], s);
    }
    g_xc2[idx] = silu_f(s);
}

// ---------------- k3: x_dbl projection + dt projection (float4 smem) --------------
__global__ __launch_bounds__(256) void k3_xproj(const float* __restrict__ Wx,
                                                const float* __restrict__ Wdt,
                                                const float* __restrict__ bdt) {
    __shared__ __align__(16) float buf[13568];
    float* sX = buf;                      // [64][68]
    float* sW = buf + 64 * 68;            // [48][68]
    const int tid = threadIdx.x;
    const int m0 = blockIdx.x * 64;
    const int row = tid >> 2, c0 = (tid & 3) * 12;

    float acc[12];
    #pragma unroll
    for (int i = 0; i < 12; i++) acc[i] = 0.0f;

    for (int k0 = 0; k0 < DI; k0 += 64) {
        __syncthreads();
        for (int idx = tid; idx < 64 * 16; idx += 256) {
            int r = idx >> 4, q = idx & 15;
            *(float4*)&sX[r * 68 + q * 4] =
                *(const float4*)&g_xc2[(size_t)(m0 + r) * DI + k0 + q * 4];
        }
        for (int idx = tid; idx < 48 * 16; idx += 256) {
            int r = idx >> 4, q = idx & 15;
            *(float4*)&sW[r * 68 + q * 4] =
                *(const float4*)&Wx[(size_t)r * DI + k0 + q * 4];
        }
        __syncthreads();
        #pragma unroll 4
        for (int q = 0; q < 16; q++) {
            float4 xv = *(const float4*)&sX[row * 68 + q * 4];
            #pragma unroll
            for (int i = 0; i < 12; i++) {
                float4 wv = *(const float4*)&sW[(c0 + i) * 68 + q * 4];
                acc[i] = fmaf(xv.x, wv.x, acc[i]);
                acc[i] = fmaf(xv.y, wv.y, acc[i]);
                acc[i] = fmaf(xv.z, wv.z, acc[i]);
                acc[i] = fmaf(xv.w, wv.w, acc[i]);
            }
        }
    }
    __syncthreads();

    float* sD   = buf;                    // [64][52]
    float* sWdt = buf + 64 * 52;          // [512][20]
    #pragma unroll
    for (int i = 0; i < 12; i++) sD[row * 52 + c0 + i] = acc[i];
    for (int idx = tid; idx < 512 * 4; idx += 256) {
        int d = idx >> 2, q = idx & 3;
        *(float4*)&sWdt[d * 20 + q * 4] = *(const float4*)&Wdt[d * 16 + q * 4];
    }
    __syncthreads();

    for (int idx = tid; idx < 64 * 32; idx += 256) {
        int r = idx >> 5, v = idx & 31;
        float val = sD[r * 52 + DTR + v];
        if (v < 16) g_Bm[(size_t)(m0 + r) * DS + v]        = val;
        else        g_Cm[(size_t)(m0 + r) * DS + (v - 16)] = val;
    }
    for (int idx = tid; idx < 64 * DI; idx += 256) {
        int r = idx >> 9, d = idx & 511;
        float a = bdt[d];
        #pragma unroll
        for (int q = 0; q < 4; q++) {
            float4 dv = *(const float4*)&sD[r * 52 + q * 4];
            float4 wv = *(const float4*)&sWdt[d * 20 + q * 4];
            a = fmaf(dv.x, wv.x, a);
            a = fmaf(dv.y, wv.y, a);
            a = fmaf(dv.z, wv.z, a);
            a = fmaf(dv.w, wv.w, a);
        }
        g_dt[(size_t)(m0 + r) * DI + d] = softplus_f(a);
    }
}

// ---------------- k4: selective scan (sync-free, A-structure fast path) ------------
// grid (200, 4), block 128: one channel per thread.
// Fast path: A = -(1..16) => dA_s = w^(s+1), w = exp(-dt): 1 MUFU per (d,t).
__global__ __launch_bounds__(128) void k4_scan(const float* __restrict__ A_log,
                                               const float* __restrict__ D_skip) {
    const int tid = threadIdx.x;
    const int b   = blockIdx.x;
    const int d   = blockIdx.y * 128 + tid;

    float Aa[DS], h[DS];
    bool fast = true;
    #pragma unroll
    for (int s = 0; s < DS; s++) {
        Aa[s] = -__expf(A_log[d * DS + s]);
        fast = fast && (fabsf(Aa[s] + (float)(s + 1)) < 1e-4f * (float)(s + 1));
        h[s] = 0.0f;
    }
    const float Dk = D_skip[d];

    const size_t rowbase = (size_t)b * TT * DI + d;
    const float* pdt = g_dt  + rowbase;
    const float* pxc = g_xc2 + rowbase;
    const float* pz  = g_z   + rowbase;
    float*       py  = g_y   + rowbase;
    const float4* pB = (const float4*)(g_Bm + (size_t)b * TT * DS);
    const float4* pC = (const float4*)(g_Cm + (size_t)b * TT * DS);

    if (fast) {
        for (int t = 0; t < TT; t++) {
            const size_t o = (size_t)t * DI;
            float dt = pdt[o], xc = pxc[o], z = pz[o];
            float Bv[DS], Cv[DS];
            #pragma unroll
            for (int q = 0; q < 4; q++) {
                float4 bq = pB[t*4 + q], cq = pC[t*4 + q];
                Bv[4*q]=bq.x; Bv[4*q+1]=bq.y; Bv[4*q+2]=bq.z; Bv[4*q+3]=bq.w;
                Cv[4*q]=cq.x; Cv[4*q+1]=cq.y; Cv[4*q+2]=cq.z; Cv[4*q+3]=cq.w;
            }
            const float du = dt * xc;
            const float w = __expf(-dt);
            float pw = w, y = 0.0f;
            #pragma unroll
            for (int s = 0; s < DS; s++) {
                h[s] = fmaf(pw, h[s], du * Bv[s]);
                y    = fmaf(h[s], Cv[s], y);
                pw  *= w;
            }
            y = fmaf(xc, Dk, y);
            py[o] = y * silu_f(z);
        }
    } else {
        for (int t = 0; t < TT; t++) {
            const size_t o = (size_t)t * DI;
            float dt = pdt[o], xc = pxc[o], z = pz[o];
            float Bv[DS], Cv[DS];
            #pragma unroll
            for (int q = 0; q < 4; q++) {
                float4 bq = pB[t*4 + q], cq = pC[t*4 + q];
                Bv[4*q]=bq.x; Bv[4*q+1]=bq.y; Bv[4*q+2]=bq.z; Bv[4*q+3]=bq.w;
                Cv[4*q]=cq.x; Cv[4*q+1]=cq.y; Cv[4*q+2]=cq.z; Cv[4*q+3]=cq.w;
            }
            const float du = dt * xc;
            float y = 0.0f;
            #pragma unroll
            for (int s = 0; s < DS; s++) {
                float dA = __expf(dt * Aa[s]);
                h[s] = fmaf(dA, h[s], du * Bv[s]);
                y    = fmaf(h[s], Cv[s], y);
            }
            y = fmaf(xc, Dk, y);
            py[o] = y * silu_f(z);
        }
    }
}

// ---------------- k5: out-proj GEMM + RMSNorm + residual — 383us-build verbatim ----
__global__ __launch_bounds__(256) void k5_gemm_out(const float* __restrict__ x,
                                                   const float* __restrict__ W,
                                                   const float* __restrict__ ln_w,
                                                   float* __restrict__ out) {
    __shared__ uint32_t sA[32][36];
    __shared__ uint32_t sB[256][36];
    __shared__ float rowsq[32];
    const int tid = threadIdx.x, lane = tid & 31, warp = tid >> 5;
    const int lr = lane >> 2, lk = lane & 3;
    const int m0 = blockIdx.x * 32;
    const int wr = (warp >> 2) * 16, wc = (warp & 3) * 64;

    if (tid < 32) rowsq[tid] = 0.0f;

    float acc[8][4];
    #pragma unroll
    for (int jj = 0; jj < 8; jj++)
        #pragma unroll
        for (int q = 0; q < 4; q++) acc[jj][q] = 0.0f;

    const int ar = tid >> 3, ac = (tid & 7) * 4;
    const int br = tid;

    for (int d0 = 0; d0 < DI; d0 += 32) {
        __syncthreads();
        {
            float4 v = *(const float4*)&g_y[(size_t)(m0 + ar) * DI + d0 + ac];
            sA[ar][ac]=f2t(v.x); sA[ar][ac+1]=f2t(v.y); sA[ar][ac+2]=f2t(v.z); sA[ar][ac+3]=f2t(v.w);
        }
        {
            const float4* p = (const float4*)(W + (size_t)br * DI + d0);
            #pragma unroll
            for (int q = 0; q < 8; q++) {
                float4 v = p[q];
                sB[br][4*q]=f2t(v.x); sB[br][4*q+1]=f2t(v.y); sB[br][4*q+2]=f2t(v.z); sB[br][4*q+3]=f2t(v.w);
            }
        }
        __syncthreads();
        #pragma unroll
        for (int kk = 0; kk < 4; kk++) {
            const int k0 = kk * 8;
            uint32_t a0 = sA[wr+lr][k0+lk],   a1 = sA[wr+8+lr][k0+lk];
            uint32_t a2 = sA[wr+lr][k0+lk+4], a3 = sA[wr+8+lr][k0+lk+4];
            #pragma unroll
            for (int jj = 0; jj < 8; jj++) {
                uint32_t b0 = sB[wc+8*jj+lr][k0+lk];
                uint32_t b1 = sB[wc+8*jj+lr][k0+lk+4];
                mma8(acc[jj], a0, a1, a2, a3, b0, b1);
            }
        }
    }

    float s0 = 0.0f, s1 = 0.0f;
    #pragma unroll
    for (int jj = 0; jj < 8; jj++) {
        s0 += acc[jj][0]*acc[jj][0] + acc[jj][1]*acc[jj][1];
        s1 += acc[jj][2]*acc[jj][2] + acc[jj][3]*acc[jj][3];
    }
    s0 += __shfl_xor_sync(0xffffffffu, s0, 1); s0 += __shfl_xor_sync(0xffffffffu, s0, 2);
    s1 += __shfl_xor_sync(0xffffffffu, s1, 1); s1 += __shfl_xor_sync(0xffffffffu, s1, 2);
    if (lk == 0) { atomicAdd(&rowsq[wr + lr], s0); atomicAdd(&rowsq[wr + 8 + lr], s1); }
    __syncthreads();

    const int r0 = wr + lr, r1 = wr + 8 + lr;
    float rms0 = rsqrtf(rowsq[r0] * (1.0f / CC) + 1e-6f);
    float rms1 = rsqrtf(rowsq[r1] * (1.0f / CC) + 1e-6f);

    const int m0r = m0 + r0, m1r = m0 + r1;
    const int t0 = m0r & 63, b0_ = m0r >> 6, n_0 = b0_ / 25, j0 = b0_ - n_0 * 25;
    const int t1 = m1r & 63, b1_ = m1r >> 6, n_1 = b1_ / 25, j1 = b1_ - n_1 * 25;
    const size_t g0 = ((size_t)(n_0 * TT + t0) * JJ + j0) * CC;
    const size_t g1 = ((size_t)(n_1 * TT + t1) * JJ + j1) * CC;
    #pragma unroll
    for (int jj = 0; jj < 8; jj++) {
        const int col = wc + 8*jj + 2*lk;
        float2 lw = *(const float2*)&ln_w[col];
        float2 x0 = *(const float2*)&x[g0 + col];
        float2 x1 = *(const float2*)&x[g1 + col];
        *(float2*)&out[g0 + col] = make_float2(fmaf(acc[jj][0]*rms0, lw.x, x0.x),
                                               fmaf(acc[jj][1]*rms0, lw.y, x0.y));
        *(float2*)&out[g1 + col] = make_float2(fmaf(acc[jj][2]*rms1, lw.x, x1.x),
                                               fmaf(acc[jj][3]*rms1, lw.y, x1.y));
    }
}

// ---------------- launch ----------------
extern "C" void kernel_launch(void* const* d_in, const int* in_sizes, int n_in,
                              void* d_out, int out_size) {
    const float* x      = (const float*)d_in[0];
    const float* W_in   = (const float*)d_in[1];
    const float* conv_w = (const float*)d_in[2];
    const float* conv_b = (const float*)d_in[3];
    const float* W_xprj = (const float*)d_in[4];
    const float* W_dt   = (const float*)d_in[5];
    const float* b_dt   = (const float*)d_in[6];
    const float* A_log  = (const float*)d_in[7];
    const float* D_skip = (const float*)d_in[8];
    const float* W_out  = (const float*)d_in[9];
    const float* ln_w   = (const float*)d_in[10];
    float* out = (float*)d_out;

    k1_gemm_in<<<dim3(BTOT, 8), 256>>>(x, W_in);
    k2_conv<<<(NROWS * DI) / 256, 256>>>(conv_w, conv_b);
    k3_xproj<<<BTOT, 256>>>(W_xprj, W_dt, b_dt);
    k4_scan<<<dim3(BTOT, 4), 128>>>(A_log, D_skip);
    k5_gemm_out<<<NROWS / 32, 256>>>(x, W_out, ln_w, out);
}